// round 1
// baseline (speedup 1.0000x reference)
#include <cuda_runtime.h>
#include <cstdint>

// Problem shape (fixed for this dataset)
constexpr int BN = 8;
constexpr int LN = 1024;
constexpr int SN = 1024;
constexpr int HN = 16;
constexpr int EN = 64;
constexpr int DN = 64;

constexpr int TQ = 16;    // queries per CTA
constexpr int KT = 128;   // keys per shared tile
constexpr int KP = 132;   // padded row stride (floats) for k_sh [EN][KP]

constexpr int NTHREADS = 256;

// ---- packed f32x2 helpers ------------------------------------------------
__device__ __forceinline__ unsigned long long splat2(float x) {
    unsigned long long r;
    asm("mov.b64 %0, {%1, %1};" : "=l"(r) : "f"(x));
    return r;
}
__device__ __forceinline__ unsigned long long pack2(float x, float y) {
    unsigned long long r;
    asm("mov.b64 %0, {%1, %2};" : "=l"(r) : "f"(x), "f"(y));
    return r;
}
__device__ __forceinline__ float2 unpack2(unsigned long long v) {
    float2 f;
    asm("mov.b64 {%0, %1}, %2;" : "=f"(f.x), "=f"(f.y) : "l"(v));
    return f;
}
__device__ __forceinline__ void fma2(unsigned long long& d,
                                     unsigned long long a,
                                     unsigned long long b) {
    asm("fma.rn.f32x2 %0, %1, %2, %0;" : "+l"(d) : "l"(a), "l"(b));
}

// Shared layout (floats): sh_z[TQ][SN] | k_sh[EN][KP] | q_sh[TQ][EN]
constexpr int SH_Z_OFF = 0;
constexpr int SH_K_OFF = TQ * SN;
constexpr int SH_Q_OFF = SH_K_OFF + EN * KP;
constexpr int SH_TOTAL = SH_Q_OFF + TQ * EN;

__global__ __launch_bounds__(NTHREADS, 2)
void sparsemax_attn_kernel(const float* __restrict__ Q,
                           const float* __restrict__ K,
                           const float* __restrict__ V,
                           float* __restrict__ O) {
    extern __shared__ float smem[];
    float* sh_z = smem + SH_Z_OFF;   // [TQ][SN]
    float* k_sh = smem + SH_K_OFF;   // [EN][KP] transposed tile
    float* q_sh = smem + SH_Q_OFF;   // [TQ][EN], pre-scaled

    const int l0 = blockIdx.x * TQ;
    const int h  = blockIdx.y;
    const int b  = blockIdx.z;
    const int tid  = threadIdx.x;
    const int lane = tid & 31;
    const int warp = tid >> 5;

    const float scale = 0.125f;  // 1/sqrt(64)

    // ---- load + pre-scale Q tile (16 q x 64 e = 256 float4, one per thread)
    {
        const int e4 = tid & 15;
        const int qi = tid >> 4;
        const float4 val = *(reinterpret_cast<const float4*>(
            Q + ((size_t)(b * LN + l0 + qi) * HN + h) * EN) + e4);
        float4 sv;
        sv.x = val.x * scale; sv.y = val.y * scale;
        sv.z = val.z * scale; sv.w = val.w * scale;
        *(reinterpret_cast<float4*>(q_sh + qi * EN) + e4) = sv;
    }

    const int qa = warp * 2;
    const int qb = qa + 1;

    // ================= Phase 1: scores z = scale * q . k =================
    for (int t = 0; t < SN / KT; ++t) {
        __syncthreads();  // q_sh ready (t==0) / k_sh consumers done (t>0)

        // stage K tile transposed into k_sh[e][j]
        {
            const float* kbase = K + ((size_t)(b * SN + t * KT) * HN + h) * EN;
            #pragma unroll
            for (int p = 0; p < (KT * EN / 4) / NTHREADS; ++p) {  // 8 iters
                const int idx = p * NTHREADS + tid;
                const int e4 = idx & 15;
                const int j  = idx >> 4;
                const float4 val = *(reinterpret_cast<const float4*>(
                    kbase + (size_t)j * HN * EN) + e4);
                k_sh[(e4 * 4 + 0) * KP + j] = val.x;
                k_sh[(e4 * 4 + 1) * KP + j] = val.y;
                k_sh[(e4 * 4 + 2) * KP + j] = val.z;
                k_sh[(e4 * 4 + 3) * KP + j] = val.w;
            }
        }
        __syncthreads();

        // each warp: 2 queries x 128 keys; each lane: 2q x 4j
        unsigned long long acc00 = 0ull, acc01 = 0ull;  // q=qa, j pairs
        unsigned long long acc10 = 0ull, acc11 = 0ull;  // q=qb
        #pragma unroll
        for (int e4 = 0; e4 < EN / 4; ++e4) {
            const float4 qav = *(reinterpret_cast<const float4*>(q_sh + qa * EN) + e4);
            const float4 qbv = *(reinterpret_cast<const float4*>(q_sh + qb * EN) + e4);
            const float qac[4] = {qav.x, qav.y, qav.z, qav.w};
            const float qbc[4] = {qbv.x, qbv.y, qbv.z, qbv.w};
            #pragma unroll
            for (int ee = 0; ee < 4; ++ee) {
                const int e = e4 * 4 + ee;
                const float4 kv = *(reinterpret_cast<const float4*>(
                    k_sh + e * KP + 4 * lane));
                const unsigned long long k01 = pack2(kv.x, kv.y);
                const unsigned long long k23 = pack2(kv.z, kv.w);
                const unsigned long long qas = splat2(qac[ee]);
                const unsigned long long qbs = splat2(qbc[ee]);
                fma2(acc00, qas, k01);
                fma2(acc01, qas, k23);
                fma2(acc10, qbs, k01);
                fma2(acc11, qbs, k23);
            }
        }
        // write scores
        {
            const float2 a0 = unpack2(acc00), a1 = unpack2(acc01);
            const float2 b0 = unpack2(acc10), b1 = unpack2(acc11);
            float4 ra; ra.x = a0.x; ra.y = a0.y; ra.z = a1.x; ra.w = a1.y;
            float4 rb; rb.x = b0.x; rb.y = b0.y; rb.z = b1.x; rb.w = b1.y;
            *reinterpret_cast<float4*>(sh_z + qa * SN + t * KT + 4 * lane) = ra;
            *reinterpret_cast<float4*>(sh_z + qb * SN + t * KT + 4 * lane) = rb;
        }
    }
    __syncthreads();

    // ========== Phase 2+3: per-warp sparsemax tau + sparse AV ==========
    const float* vbase = V + ((size_t)b * SN * HN + h) * DN;  // + j*HN*DN + d

    for (int qq = 0; qq < 2; ++qq) {
        const int qi = warp * 2 + qq;
        const float* zrow = sh_z + qi * SN;

        // Michelot: tau0 from full sum
        float s = 0.f;
        #pragma unroll 8
        for (int i = lane; i < SN; i += 32) s += zrow[i];
        #pragma unroll
        for (int off = 16; off > 0; off >>= 1)
            s += __shfl_xor_sync(0xffffffffu, s, off);
        float tau = (s - 1.0f) * (1.0f / SN);

        for (int it = 0; it < 64; ++it) {
            float s2 = 0.f;
            int c = 0;
            #pragma unroll 8
            for (int i = lane; i < SN; i += 32) {
                const float z = zrow[i];
                if (z > tau) { s2 += z; ++c; }
            }
            #pragma unroll
            for (int off = 16; off > 0; off >>= 1) {
                s2 += __shfl_xor_sync(0xffffffffu, s2, off);
                c  += __shfl_xor_sync(0xffffffffu, c,  off);
            }
            const float tn = (s2 - 1.0f) / (float)c;
            if (!(tn > tau)) break;   // converged (active set fixed)
            tau = tn;
        }

        // sparse AV: gather only support rows
        float o0 = 0.f, o1 = 0.f;  // d = lane, lane+32
        for (int jb = 0; jb < SN; jb += 32) {
            const float p = zrow[jb + lane] - tau;
            unsigned m = __ballot_sync(0xffffffffu, p > 0.f);
            while (m) {
                const int bit = __ffs(m) - 1;
                m &= (m - 1);
                const float pj = __shfl_sync(0xffffffffu, p, bit);
                const float* vr = vbase + (size_t)(jb + bit) * HN * DN;
                o0 += pj * vr[lane];
                o1 += pj * vr[lane + 32];
            }
        }

        float* orow = O + ((size_t)(b * LN + l0 + qi) * HN + h) * DN;
        orow[lane]      = o0;
        orow[lane + 32] = o1;
    }
}

extern "C" void kernel_launch(void* const* d_in, const int* in_sizes, int n_in,
                              void* d_out, int out_size) {
    const float* Q = (const float*)d_in[0];
    const float* K = (const float*)d_in[1];
    const float* V = (const float*)d_in[2];
    float* O = (float*)d_out;

    const size_t smem_bytes = (size_t)SH_TOTAL * sizeof(float);
    cudaFuncSetAttribute(sparsemax_attn_kernel,
                         cudaFuncAttributeMaxDynamicSharedMemorySize,
                         (int)smem_bytes);

    dim3 grid(LN / TQ, HN, BN);
    sparsemax_attn_kernel<<<grid, NTHREADS, smem_bytes>>>(Q, K, V, O);
}

// round 3
// speedup vs baseline: 1.1678x; 1.1678x over previous
#include <cuda_runtime.h>
#include <cstdint>

using ull = unsigned long long;

// Problem shape (fixed for this dataset)
constexpr int BN = 8;
constexpr int LN = 1024;
constexpr int SN = 1024;
constexpr int HN = 16;
constexpr int EN = 64;
constexpr int DN = 64;

constexpr int TQ    = 16;    // queries per CTA
constexpr int CHUNK = 256;   // keys per staged chunk
constexpr int NCH   = SN / CHUNK;   // 4
constexpr int NTHREADS = 256;       // 8 warps

// Shared layout (floats): z[TQ][SN] | kbuf[2][EN][CHUNK] | qT[EN][TQ]
constexpr int KBUF_FLOATS = EN * CHUNK;               // 16384
constexpr int Z_OFF  = 0;                             // 16384 floats
constexpr int KB_OFF = TQ * SN;                       // 2*16384 floats
constexpr int Q_OFF  = KB_OFF + 2 * KBUF_FLOATS;      // 1024 floats
constexpr int SH_TOTAL = Q_OFF + EN * TQ;             // 50176 floats = 196 KB

// ---- packed f32x2 helpers ------------------------------------------------
__device__ __forceinline__ ull splat2(float x) {
    ull r;
    asm("mov.b64 %0, {%1, %1};" : "=l"(r) : "f"(x));
    return r;
}
__device__ __forceinline__ float2 unpack2(ull v) {
    float2 f;
    asm("mov.b64 {%0, %1}, %2;" : "=f"(f.x), "=f"(f.y) : "l"(v));
    return f;
}
__device__ __forceinline__ void fma2(ull& d, ull a, ull b) {
    asm("fma.rn.f32x2 %0, %1, %2, %0;" : "+l"(d) : "l"(a), "l"(b));
}

__global__ __launch_bounds__(NTHREADS, 1)
void sparsemax_attn_kernel(const float* __restrict__ Q,
                           const float* __restrict__ K,
                           const float* __restrict__ V,
                           float* __restrict__ O) {
    extern __shared__ float smem[];
    float* sh_z = smem + Z_OFF;    // [TQ][SN]
    float* qsh  = smem + Q_OFF;    // [EN][TQ] transposed, pre-scaled

    const int l0 = blockIdx.x * TQ;
    const int h  = blockIdx.y;
    const int b  = blockIdx.z;
    const int tid  = threadIdx.x;
    const int lane = tid & 31;
    const int warp = tid >> 5;

    const float scale = 0.125f;  // 1/sqrt(64)

    // ---- load + pre-scale + transpose Q tile into qsh[e][q] ----
    {
        const int e4 = tid & 15;
        const int qi = tid >> 4;
        const float4 v = *(reinterpret_cast<const float4*>(
            Q + ((size_t)(b * LN + l0 + qi) * HN + h) * EN) + e4);
        qsh[(4 * e4 + 0) * TQ + qi] = v.x * scale;
        qsh[(4 * e4 + 1) * TQ + qi] = v.y * scale;
        qsh[(4 * e4 + 2) * TQ + qi] = v.z * scale;
        qsh[(4 * e4 + 3) * TQ + qi] = v.w * scale;
    }

    // ---- staging mapping: thread = (e4s, jrs), 16 float4 per chunk ----
    const int e4s = tid & 15;
    const int jrs = tid >> 4;
    const float* kgbase = K + ((size_t)(b * SN) * HN + h) * EN + 4 * e4s;

    float4 st[16];  // register staging buffer (prefetch of next chunk)

    // prologue: fetch + stage chunk 0
    {
        const float* kg = kgbase + (size_t)jrs * HN * EN;
        #pragma unroll
        for (int i = 0; i < 16; ++i)
            st[i] = *reinterpret_cast<const float4*>(kg + (size_t)i * 16 * HN * EN);
        float* kb = smem + KB_OFF;  // buf 0
        #pragma unroll
        for (int i = 0; i < 16; ++i) {
            const int j = i * 16 + jrs;
            const int blkv = j >> 2;
            const int sb = (blkv & 32) | ((blkv ^ e4s) & 31);
            float* p = kb + (4 * e4s) * CHUNK + 4 * sb + (j & 3);
            p[0 * CHUNK] = st[i].x;
            p[1 * CHUNK] = st[i].y;
            p[2 * CHUNK] = st[i].z;
            p[3 * CHUNK] = st[i].w;
        }
    }
    __syncthreads();

    // ---- compute mapping: warp = (qg: 8 queries, jt: 64 keys), lane = 8q x 2j
    const int qg  = warp & 1;        // 0..1 -> q base 8*qg
    const int jt  = warp >> 1;       // 0..3 -> j base 64*jt (within chunk)
    const int blk = 16 * jt + (lane >> 1);
    const int lo2 = (lane & 1) * 2;  // 0 or 2 within 16B block

    for (int c = 0; c < NCH; ++c) {
        // prefetch next chunk's K into registers (overlaps compute)
        if (c + 1 < NCH) {
            const float* kg = kgbase + (size_t)((c + 1) * CHUNK + jrs) * HN * EN;
            #pragma unroll
            for (int i = 0; i < 16; ++i)
                st[i] = *reinterpret_cast<const float4*>(kg + (size_t)i * 16 * HN * EN);
        }

        const float* kb = smem + KB_OFF + (c & 1) * KBUF_FLOATS;

        ull acc[4][2];
        #pragma unroll
        for (int qp = 0; qp < 4; ++qp) { acc[qp][0] = 0ull; acc[qp][1] = 0ull; }

        #pragma unroll 4
        for (int e = 0; e < EN; ++e) {
            const int sb = (blk & 32) | ((blk ^ (e >> 2)) & 31);
            const float2 kv = *reinterpret_cast<const float2*>(
                kb + e * CHUNK + 4 * sb + lo2);
            const ulonglong2 q01 = *reinterpret_cast<const ulonglong2*>(
                qsh + e * TQ + 8 * qg);        // q0..q3 as 2 packed pairs
            const ulonglong2 q23 = *reinterpret_cast<const ulonglong2*>(
                qsh + e * TQ + 8 * qg + 4);    // q4..q7
            const ull k0 = splat2(kv.x);
            const ull k1 = splat2(kv.y);
            fma2(acc[0][0], q01.x, k0); fma2(acc[0][1], q01.x, k1);
            fma2(acc[1][0], q01.y, k0); fma2(acc[1][1], q01.y, k1);
            fma2(acc[2][0], q23.x, k0); fma2(acc[2][1], q23.x, k1);
            fma2(acc[3][0], q23.y, k0); fma2(acc[3][1], q23.y, k1);
        }

        // write scores for this chunk: 8 rows x 2 cols per lane
        {
            const int jcol = c * CHUNK + 64 * jt + 2 * lane;
            #pragma unroll
            for (int qp = 0; qp < 4; ++qp) {
                const float2 a0 = unpack2(acc[qp][0]);
                const float2 a1 = unpack2(acc[qp][1]);
                float2 ev; ev.x = a0.x; ev.y = a1.x;
                float2 od; od.x = a0.y; od.y = a1.y;
                *reinterpret_cast<float2*>(sh_z + (8 * qg + 2 * qp    ) * SN + jcol) = ev;
                *reinterpret_cast<float2*>(sh_z + (8 * qg + 2 * qp + 1) * SN + jcol) = od;
            }
        }

        // stage prefetched chunk into the other buffer (disjoint from readers)
        if (c + 1 < NCH) {
            float* kbn = smem + KB_OFF + ((c + 1) & 1) * KBUF_FLOATS;
            #pragma unroll
            for (int i = 0; i < 16; ++i) {
                const int j = i * 16 + jrs;
                const int blkv = j >> 2;
                const int sb = (blkv & 32) | ((blkv ^ e4s) & 31);
                float* p = kbn + (4 * e4s) * CHUNK + 4 * sb + (j & 3);
                p[0 * CHUNK] = st[i].x;
                p[1 * CHUNK] = st[i].y;
                p[2 * CHUNK] = st[i].z;
                p[3 * CHUNK] = st[i].w;
            }
        }
        __syncthreads();
    }

    // ========== Phase 2+3: per-warp sparsemax tau + sparse AV ==========
    const float* vbase = V + ((size_t)b * SN * HN + h) * DN;  // + j*HN*DN + d

    for (int qq = 0; qq < 2; ++qq) {
        const int qi = warp * 2 + qq;
        const float* zrow = sh_z + qi * SN;
        const float4* z4 = reinterpret_cast<const float4*>(zrow);

        // Michelot: tau0 from full sum (vectorized)
        float s = 0.f;
        #pragma unroll
        for (int i = 0; i < SN / 128; ++i) {
            const float4 v = z4[lane + 32 * i];
            s += (v.x + v.y) + (v.z + v.w);
        }
        #pragma unroll
        for (int off = 16; off > 0; off >>= 1)
            s += __shfl_xor_sync(0xffffffffu, s, off);
        float tau = (s - 1.0f) * (1.0f / SN);

        for (int it = 0; it < 64; ++it) {
            float s2 = 0.f;
            int cnt = 0;
            #pragma unroll
            for (int i = 0; i < SN / 128; ++i) {
                const float4 v = z4[lane + 32 * i];
                if (v.x > tau) { s2 += v.x; ++cnt; }
                if (v.y > tau) { s2 += v.y; ++cnt; }
                if (v.z > tau) { s2 += v.z; ++cnt; }
                if (v.w > tau) { s2 += v.w; ++cnt; }
            }
            #pragma unroll
            for (int off = 16; off > 0; off >>= 1) {
                s2  += __shfl_xor_sync(0xffffffffu, s2, off);
                cnt += __shfl_xor_sync(0xffffffffu, cnt, off);
            }
            const float tn = (s2 - 1.0f) / (float)cnt;
            if (!(tn > tau)) break;   // converged (active set fixed)
            tau = tn;
        }

        // sparse AV: gather only support rows
        float o0 = 0.f, o1 = 0.f;  // d = lane, lane+32
        for (int jb = 0; jb < SN; jb += 32) {
            const float p = zrow[jb + lane] - tau;
            unsigned m = __ballot_sync(0xffffffffu, p > 0.f);
            while (m) {
                const int bit = __ffs(m) - 1;
                m &= (m - 1);
                const float pj = __shfl_sync(0xffffffffu, p, bit);
                const float* vr = vbase + (size_t)(jb + bit) * HN * DN;
                o0 += pj * vr[lane];
                o1 += pj * vr[lane + 32];
            }
        }

        float* orow = O + ((size_t)(b * LN + l0 + qi) * HN + h) * DN;
        orow[lane]      = o0;
        orow[lane + 32] = o1;
    }
}

extern "C" void kernel_launch(void* const* d_in, const int* in_sizes, int n_in,
                              void* d_out, int out_size) {
    const float* Q = (const float*)d_in[0];
    const float* K = (const float*)d_in[1];
    const float* V = (const float*)d_in[2];
    float* O = (float*)d_out;

    const size_t smem_bytes = (size_t)SH_TOTAL * sizeof(float);
    cudaFuncSetAttribute(sparsemax_attn_kernel,
                         cudaFuncAttributeMaxDynamicSharedMemorySize,
                         (int)smem_bytes);

    dim3 grid(LN / TQ, HN, BN);
    sparsemax_attn_kernel<<<grid, NTHREADS, smem_bytes>>>(Q, K, V, O);
}

// round 7
// speedup vs baseline: 3.2709x; 2.8008x over previous
#include <cuda_runtime.h>
#include <cuda_bf16.h>
#include <cstdint>

// ---------------- problem shape (fixed) ----------------
constexpr int BN = 8, LN = 1024, SN = 1024, HN = 16, EN = 64, DN = 64;

constexpr int MQ  = 128;           // queries per CTA
constexpr int NK  = 64;            // keys per chunk
constexpr int NCH = SN / NK;       // 16
constexpr int NTHREADS = 512;      // 16 warps
constexpr int CAPQ = 24;           // candidate capacity per (row, quarter)

constexpr int QK_STRIDE = 72;      // bf16 elems per smem row (144 B)
constexpr int Z_STRIDE  = 76;      // f32 per z row

// ---------------- smem layout (bytes) ----------------
constexpr int QTILE   = MQ * QK_STRIDE * 2;        // 18432
constexpr int OFF_QHI = 0;
constexpr int OFF_QLO = OFF_QHI + QTILE;           // 18432
constexpr int KTILE   = NK * QK_STRIDE * 2;        // 9216 (hi or lo)
constexpr int KBUF    = 2 * KTILE;                 // 18432 (hi+lo)
constexpr int OFF_KB  = OFF_QLO + QTILE;           // 36864 ; 2 buffers
constexpr int OFF_Z   = OFF_KB + 2 * KBUF;         // 73728
constexpr int OFF_CV  = OFF_Z + MQ * Z_STRIDE * 4; // 112640 ; float[128*4*CAPQ]
constexpr int OFF_CI  = OFF_CV + MQ * 4 * CAPQ * 4;// 161792 ; u16
constexpr int OFF_CNT = OFF_CI + MQ * 4 * CAPQ * 2;// 186368 ; int[512]
constexpr int SMEM_BYTES = OFF_CNT + MQ * 4 * 4;   // 188416

// ---------------- prepped bf16 hi/lo tensors ([b][h][l|s][e]) ----------------
__device__ __nv_bfloat16 g_qhi[(size_t)BN*HN*LN*EN];
__device__ __nv_bfloat16 g_qlo[(size_t)BN*HN*LN*EN];
__device__ __nv_bfloat16 g_khi[(size_t)BN*HN*SN*EN];
__device__ __nv_bfloat16 g_klo[(size_t)BN*HN*SN*EN];

// ---------------- PTX helpers ----------------
__device__ __forceinline__ uint32_t smem_to_u32(const void* p) {
    uint32_t a;
    asm("{ .reg .u64 t; cvta.to.shared.u64 t, %1; cvt.u32.u64 %0, t; }" : "=r"(a) : "l"(p));
    return a;
}
__device__ __forceinline__ void ldsm_x4(uint32_t r[4], uint32_t addr) {
    asm volatile("ldmatrix.sync.aligned.m8n8.x4.shared.b16 {%0,%1,%2,%3}, [%4];"
                 : "=r"(r[0]), "=r"(r[1]), "=r"(r[2]), "=r"(r[3]) : "r"(addr));
}
__device__ __forceinline__ void mma_bf16(float d[4], const uint32_t a[4],
                                         uint32_t b0, uint32_t b1) {
    asm volatile("mma.sync.aligned.m16n8k16.row.col.f32.bf16.bf16.f32 "
                 "{%0,%1,%2,%3}, {%4,%5,%6,%7}, {%8,%9}, {%0,%1,%2,%3};"
                 : "+f"(d[0]), "+f"(d[1]), "+f"(d[2]), "+f"(d[3])
                 : "r"(a[0]), "r"(a[1]), "r"(a[2]), "r"(a[3]), "r"(b0), "r"(b1));
}

// ---------------- prep: fp32 -> bf16 hi/lo, [b,l,h,e] -> [b,h,l,e] ----------------
__global__ void prep_kernel(const float* __restrict__ Q, const float* __restrict__ K) {
    const size_t total = (size_t)BN * LN * HN * EN;
    for (size_t i = (size_t)blockIdx.x * blockDim.x + threadIdx.x; i < total;
         i += (size_t)gridDim.x * blockDim.x) {
        const int e = (int)(i & 63);
        const int h = (int)((i >> 6) & 15);
        const int l = (int)((i >> 10) & 1023);
        const int b = (int)(i >> 20);
        const size_t o = ((((size_t)b * HN + h) * LN + l) << 6) + e;

        float q = Q[i] * 0.125f;                        // fold 1/sqrt(E)
        __nv_bfloat16 qh = __float2bfloat16(q);
        g_qhi[o] = qh;
        g_qlo[o] = __float2bfloat16(q - __bfloat162float(qh));

        float k = K[i];
        __nv_bfloat16 kh = __float2bfloat16(k);
        g_khi[o] = kh;
        g_klo[o] = __float2bfloat16(k - __bfloat162float(kh));
    }
}

// ---------------- main kernel ----------------
__global__ __launch_bounds__(NTHREADS, 1)
void sparsemax_attn_mma(const float* __restrict__ V, float* __restrict__ O) {
    extern __shared__ char smem[];
    const uint32_t sb = smem_to_u32(smem);
    const int tid = threadIdx.x, lane = tid & 31, warp = tid >> 5;
    const int wq = warp & 3, wk = warp >> 2;
    const int l0 = blockIdx.x * MQ, h = blockIdx.y, b = blockIdx.z;
    const size_t bh = (size_t)b * HN + h;

    // ---- stage Q hi/lo into padded smem tiles ----
    {
        const uint4* qh = reinterpret_cast<const uint4*>(g_qhi + ((bh * LN + l0) << 6));
        const uint4* ql = reinterpret_cast<const uint4*>(g_qlo + ((bh * LN + l0) << 6));
        #pragma unroll
        for (int p = 0; p < 2; ++p) {
            const int slot = tid + NTHREADS * p;   // 1024 slots
            const int row = slot >> 3, q8 = slot & 7;
            const int dst = row * 144 + q8 * 16;
            *reinterpret_cast<uint4*>(smem + OFF_QHI + dst) = qh[slot];
            *reinterpret_cast<uint4*>(smem + OFF_QLO + dst) = ql[slot];
        }
    }

    // ---- stage K chunk 0 ----
    const int krow = tid >> 3, kq8 = tid & 7;
    const uint4* gkh = reinterpret_cast<const uint4*>(g_khi + ((bh * SN) << 6));
    const uint4* gkl = reinterpret_cast<const uint4*>(g_klo + ((bh * SN) << 6));
    {
        const int slot = krow * 8 + kq8;                  // = tid
        const int dst = krow * 144 + kq8 * 16;
        *reinterpret_cast<uint4*>(smem + OFF_KB + dst) = gkh[slot];
        *reinterpret_cast<uint4*>(smem + OFF_KB + KTILE + dst) = gkl[slot];
    }
    __syncthreads();

    // ---- ldmatrix lane addressing ----
    const int lrow  = lane & 15;
    const int lhalf = (lane >> 4) * 16;

    // cache A-hi fragments for the whole CTA lifetime: [mt][ks][4]
    uint32_t ah[2][4][4];
    uint32_t qloA[2];  // per-mt base addrs for A-lo reloads
    #pragma unroll
    for (int mt = 0; mt < 2; ++mt) {
        const uint32_t rowoff = (uint32_t)(32 * wq + 16 * mt + lrow) * 144 + lhalf;
        qloA[mt] = sb + OFF_QLO + rowoff;
        #pragma unroll
        for (int ks = 0; ks < 4; ++ks)
            ldsm_x4(ah[mt][ks], sb + OFF_QHI + rowoff + 32 * ks);
    }

    // per-lane candidate state: row = warp*8 + (lane>>2), quarter = lane&3
    const int rsub = lane >> 2, t4 = lane & 3;
    const int myrow = warp * 8 + rsub;
    float runmax = -1e30f;
    float thr    = -1e30f;   // max(runmax-1, streaming tau lower bound)
    float csum   = 0.f;      // sum of current candidates (this lane's list)
    int cnt = 0;
    float* cv = reinterpret_cast<float*>(smem + OFF_CV) + (myrow * 4 + t4) * CAPQ;
    uint16_t* cix = reinterpret_cast<uint16_t*>(smem + OFF_CI) + (myrow * 4 + t4) * CAPQ;

    const uint32_t kbRow = (uint32_t)(16 * wk + lrow) * 144 + lhalf;
    const int g = lane >> 2, tt = lane & 3;

    for (int c = 0; c < NCH; ++c) {
        const int buf = c & 1;
        const uint32_t kbh = sb + OFF_KB + buf * KBUF + kbRow;
        const uint32_t kbl = kbh + KTILE;

        float acc[2][2][4];
        #pragma unroll
        for (int mt = 0; mt < 2; ++mt)
            #pragma unroll
            for (int nt = 0; nt < 2; ++nt)
                #pragma unroll
                for (int i = 0; i < 4; ++i) acc[mt][nt][i] = 0.f;

        #pragma unroll
        for (int ks = 0; ks < 4; ++ks) {
            uint32_t bhf[4], blf[4], al0[4], al1[4];
            ldsm_x4(bhf, kbh + 32 * ks);
            ldsm_x4(blf, kbl + 32 * ks);
            ldsm_x4(al0, qloA[0] + 32 * ks);
            ldsm_x4(al1, qloA[1] + 32 * ks);

            mma_bf16(acc[0][0], ah[0][ks], bhf[0], bhf[2]);
            mma_bf16(acc[0][1], ah[0][ks], bhf[1], bhf[3]);
            mma_bf16(acc[1][0], ah[1][ks], bhf[0], bhf[2]);
            mma_bf16(acc[1][1], ah[1][ks], bhf[1], bhf[3]);

            mma_bf16(acc[0][0], ah[0][ks], blf[0], blf[2]);
            mma_bf16(acc[0][1], ah[0][ks], blf[1], blf[3]);
            mma_bf16(acc[1][0], ah[1][ks], blf[0], blf[2]);
            mma_bf16(acc[1][1], ah[1][ks], blf[1], blf[3]);

            mma_bf16(acc[0][0], al0, bhf[0], bhf[2]);
            mma_bf16(acc[0][1], al0, bhf[1], bhf[3]);
            mma_bf16(acc[1][0], al1, bhf[0], bhf[2]);
            mma_bf16(acc[1][1], al1, bhf[1], bhf[3]);
        }

        // prefetch next K chunk into registers (hide L2 latency behind z store/scan)
        uint4 pfh, pfl;
        if (c + 1 < NCH) {
            const int slot = ((c + 1) * NK + krow) * 8 + kq8;
            pfh = gkh[slot];
            pfl = gkl[slot];
        }

        // ---- write scores to z ----
        #pragma unroll
        for (int mt = 0; mt < 2; ++mt)
            #pragma unroll
            for (int nt = 0; nt < 2; ++nt) {
                const int row0 = 32 * wq + 16 * mt + g;
                const int col  = 16 * wk + 8 * nt + 2 * tt;
                float2 lo2; lo2.x = acc[mt][nt][0]; lo2.y = acc[mt][nt][1];
                float2 hi2; hi2.x = acc[mt][nt][2]; hi2.y = acc[mt][nt][3];
                *reinterpret_cast<float2*>(smem + OFF_Z + ((size_t)row0 * Z_STRIDE + col) * 4) = lo2;
                *reinterpret_cast<float2*>(smem + OFF_Z + ((size_t)(row0 + 8) * Z_STRIDE + col) * 4) = hi2;
            }
        __syncthreads();

        // ---- scan: lane owns (myrow, cols 16*t4 .. 16*t4+15) ----
        {
            const float* zr = reinterpret_cast<const float*>(smem + OFF_Z)
                              + (size_t)myrow * Z_STRIDE + 16 * t4;
            float v[16];
            #pragma unroll
            for (int i = 0; i < 4; ++i) {
                const float4 f = reinterpret_cast<const float4*>(zr)[i];
                v[4*i+0] = f.x; v[4*i+1] = f.y; v[4*i+2] = f.z; v[4*i+3] = f.w;
            }
            float bmax = v[0];
            #pragma unroll
            for (int i = 1; i < 16; ++i) bmax = fmaxf(bmax, v[i]);
            bmax = fmaxf(bmax, __shfl_xor_sync(0xffffffffu, bmax, 1));
            bmax = fmaxf(bmax, __shfl_xor_sync(0xffffffffu, bmax, 2));
            runmax = fmaxf(runmax, bmax);
            thr = fmaxf(thr, runmax - 1.0f);

            #pragma unroll
            for (int i = 0; i < 16; ++i) {
                if (v[i] > thr) {
                    if (cnt == CAPQ) {       // recompact with freshest thr
                        int m = 0; float s = 0.f;
                        for (int q = 0; q < CAPQ; ++q) {
                            const float cq = cv[q];
                            if (cq > thr) { cv[m] = cq; cix[m] = cix[q]; s += cq; ++m; }
                        }
                        cnt = m; csum = s;
                    }
                    if (cnt < CAPQ) {
                        cv[cnt] = v[i];
                        cix[cnt] = (uint16_t)(c * NK + 16 * t4 + i);
                        csum += v[i];
                        ++cnt;
                    } else {
                        // evict min if new value larger (practically unreachable)
                        int am = 0; float mn = cv[0];
                        for (int q = 1; q < CAPQ; ++q)
                            if (cv[q] < mn) { mn = cv[q]; am = q; }
                        if (v[i] > mn) {
                            csum += v[i] - mn;
                            cv[am] = v[i];
                            cix[am] = (uint16_t)(c * NK + 16 * t4 + i);
                        }
                    }
                }
            }

            // streaming tau lower bound from current candidate set (valid for
            // any subset C of the row: (sum_C - 1)/|C| <= tau*)
            float sq = csum; int cq = cnt;
            sq += __shfl_xor_sync(0xffffffffu, sq, 1);
            sq += __shfl_xor_sync(0xffffffffu, sq, 2);
            cq += __shfl_xor_sync(0xffffffffu, cq, 1);
            cq += __shfl_xor_sync(0xffffffffu, cq, 2);
            if (cq > 0) thr = fmaxf(thr, (sq - 1.0f) / (float)cq);
        }

        // ---- stage prefetched chunk into the other buffer ----
        if (c + 1 < NCH) {
            const int dst = krow * 144 + kq8 * 16;
            char* kb = smem + OFF_KB + ((c + 1) & 1) * KBUF;
            *reinterpret_cast<uint4*>(kb + dst) = pfh;
            *reinterpret_cast<uint4*>(kb + KTILE + dst) = pfl;
        }
        __syncthreads();
    }

    // ---- quad-cooperative Michelot tau (exact on candidate superset) ----
    {
        float s = csum;
        s += __shfl_xor_sync(0xffffffffu, s, 1);
        s += __shfl_xor_sync(0xffffffffu, s, 2);
        int ctot = cnt;
        ctot += __shfl_xor_sync(0xffffffffu, ctot, 1);
        ctot += __shfl_xor_sync(0xffffffffu, ctot, 2);
        float tau = (s - 1.0f) / (float)ctot;

        bool changed = true;
        while (__any_sync(0xffffffffu, changed)) {
            float s2 = 0.f; int c2 = 0;
            for (int i = 0; i < cnt; ++i) {
                const float vv = cv[i];
                if (vv > tau) { s2 += vv; ++c2; }
            }
            s2 += __shfl_xor_sync(0xffffffffu, s2, 1);
            s2 += __shfl_xor_sync(0xffffffffu, s2, 2);
            c2 += __shfl_xor_sync(0xffffffffu, c2, 1);
            c2 += __shfl_xor_sync(0xffffffffu, c2, 2);
            const float tn = (s2 - 1.0f) / (float)c2;
            changed = (tn > tau);
            if (changed) tau = tn;
        }

        // compact to p = v - tau > 0
        int m = 0;
        for (int i = 0; i < cnt; ++i) {
            const float vv = cv[i];
            if (vv > tau) { cv[m] = vv - tau; cix[m] = cix[i]; ++m; }
        }
        reinterpret_cast<int*>(smem + OFF_CNT)[myrow * 4 + t4] = m;
    }
    __syncthreads();

    // ---- sparse AV: warp w -> rows 8w..8w+7; lane covers d=lane, lane+32 ----
    {
        const float* vb = V + ((size_t)b * SN * HN + h) * DN;
        const int* scnt = reinterpret_cast<const int*>(smem + OFF_CNT);
        for (int rr = 0; rr < 8; ++rr) {
            const int row = warp * 8 + rr;
            float o0 = 0.f, o1 = 0.f;
            #pragma unroll
            for (int t = 0; t < 4; ++t) {
                const int m = scnt[row * 4 + t];
                const float* cvr = reinterpret_cast<const float*>(smem + OFF_CV)
                                   + (row * 4 + t) * CAPQ;
                const uint16_t* cir = reinterpret_cast<const uint16_t*>(smem + OFF_CI)
                                   + (row * 4 + t) * CAPQ;
                for (int i = 0; i < m; ++i) {
                    const float p = cvr[i];
                    const int j = cir[i];
                    const float* vr = vb + (size_t)j * HN * DN;
                    o0 += p * vr[lane];
                    o1 += p * vr[lane + 32];
                }
            }
            float* orow = O + (((size_t)b * LN + l0 + row) * HN + h) * DN;
            orow[lane]      = o0;
            orow[lane + 32] = o1;
        }
    }
}

// ---------------- launch ----------------
extern "C" void kernel_launch(void* const* d_in, const int* in_sizes, int n_in,
                              void* d_out, int out_size) {
    const float* Q = (const float*)d_in[0];
    const float* K = (const float*)d_in[1];
    const float* V = (const float*)d_in[2];
    float* O = (float*)d_out;

    prep_kernel<<<4096, 256>>>(Q, K);

    cudaFuncSetAttribute(sparsemax_attn_mma,
                         cudaFuncAttributeMaxDynamicSharedMemorySize, SMEM_BYTES);
    dim3 grid(LN / MQ, HN, BN);
    sparsemax_attn_mma<<<grid, NTHREADS, SMEM_BYTES>>>(V, O);
}